// round 11
// baseline (speedup 1.0000x reference)
#include <cuda_runtime.h>
#include <math.h>

#define NCELL 16
#define CH    256

struct Basis { float B[32 * 15]; };   // B[k*15+j] = B_BASIS[k][j] (fp32)

// Tables in t-coordinates (t = p*16), per (cell m, channel c):
//  g_psi[m*CH+c] = (E, F16)   closed-form step  t' = E*t + F16   (F16 = 16*F)
//  g_eul[m*CH+c] = (EA,EB16)  Euler substep     t' = EA*t + EB16 (EB16 = 16*EB)
__device__ float2 g_psi[NCELL * CH];
__device__ float2 g_eul[NCELL * CH];

// ---------------------------------------------------------------------------
// Host: reproduce np.linalg.svd(L) null-space rows. LAPACK dgesdd Path 4t
// (M=17 < N=32, N >= MNTHR): rows 17..31 of VT are rows 17..31 of
// Q = H(17)...H(1) from the LQ factorization of L. Pure fp64 arithmetic,
// deterministic, depends only on compile-time constants -> host-side OK.
// ---------------------------------------------------------------------------
static void compute_basis_host(Basis* out)
{
    double Ad[17][32];
    double Qd[32][32];
    double tau[17];

    for (int i = 0; i < 17; i++)
        for (int j = 0; j < 32; j++) Ad[i][j] = 0.0;

    for (int k = 1; k < NCELL; k++) {
        double xk = (double)k / (double)NCELL;
        Ad[k - 1][2 * (k - 1)]     =  xk;
        Ad[k - 1][2 * (k - 1) + 1] =  1.0;
        Ad[k - 1][2 * k]           = -xk;
        Ad[k - 1][2 * k + 1]       = -1.0;
    }
    Ad[NCELL - 1][1]         = 1.0;
    Ad[NCELL][2 * NCELL - 2] = 1.0;
    Ad[NCELL][2 * NCELL - 1] = 1.0;

    // LQ with LAPACK dlarfg sign convention
    for (int i = 0; i < 17; i++) {
        double xn2 = 0.0;
        for (int j = i + 1; j < 32; j++) xn2 += Ad[i][j] * Ad[i][j];
        double alpha = Ad[i][i];
        if (xn2 == 0.0) {
            tau[i] = 0.0;
        } else {
            double r    = sqrt(alpha * alpha + xn2);
            double beta = (alpha >= 0.0) ? -r : r;
            tau[i] = (beta - alpha) / beta;
            double sc = 1.0 / (alpha - beta);
            for (int j = i + 1; j < 32; j++) Ad[i][j] *= sc;
            Ad[i][i] = beta;
        }
        double ti = tau[i];
        if (ti != 0.0) {
            for (int rr = i + 1; rr < 17; rr++) {
                double w = Ad[rr][i];
                for (int j = i + 1; j < 32; j++) w += Ad[rr][j] * Ad[i][j];
                w *= ti;
                Ad[rr][i] -= w;
                for (int j = i + 1; j < 32; j++) Ad[rr][j] -= w * Ad[i][j];
            }
        }
    }

    // Q = H(17)...H(1), applied to I (M := H(i)*M, i ascending)
    for (int i = 0; i < 32; i++)
        for (int j = 0; j < 32; j++) Qd[i][j] = (i == j) ? 1.0 : 0.0;

    for (int i = 0; i < 17; i++) {
        double ti = tau[i];
        if (ti == 0.0) continue;
        for (int jc = 0; jc < 32; jc++) {
            double s = Qd[i][jc];
            for (int j = i + 1; j < 32; j++) s += Ad[i][j] * Qd[j][jc];
            s *= ti;
            Qd[i][jc] -= s;
            for (int j = i + 1; j < 32; j++) Qd[j][jc] -= Ad[i][j] * s;
        }
    }

    // B_BASIS[k][j] = VT[17+j][k] = Qd[17+j][k], cast to fp32
    for (int k = 0; k < 32; k++)
        for (int j = 0; j < 15; j++)
            out->B[k * 15 + j] = (float)Qd[17 + j][k];
}

// ---------------------------------------------------------------------------
// Tiny setup kernel: per-(cell,channel) affine tables (t-coords) + theta copy.
// ---------------------------------------------------------------------------
__global__ void cpab_setup(const float* __restrict__ theta,
                           const void*  __restrict__ timep,
                           float* __restrict__ out_tail, int tail_n,
                           Basis bb)
{
    const int c = threadIdx.x;     // channel

    // time scalar: robust to int32/int64/float32 storage (value is 1)
    int   iv = *(const int*)timep;
    float fv = *(const float*)timep;
    float t;
    if (iv > 0 && iv < 1000000)        t = (float)iv;
    else if (fv > 0.0f && fv < 1.0e6f) t = fv;
    else                               t = 1.0f;
    float dt  = t / 10.0f;     // NSTEPS1 = 10
    float ddt = dt / 5.0f;     // NSTEPS2 = 5

    float th[15];
    #pragma unroll
    for (int j = 0; j < 15; j++) th[j] = theta[c * 15 + j];

    #pragma unroll
    for (int m = 0; m < NCELL; m++) {
        float af = 0.0f, bf = 0.0f;
        #pragma unroll
        for (int j = 0; j < 15; j++) {
            af = fmaf(th[j], bb.B[(2 * m) * 15 + j],     af);
            bf = fmaf(th[j], bb.B[(2 * m + 1) * 15 + j], bf);
        }
        float E, F;
        if (fabsf(af) > 1e-7f) {
            float eta = expf(dt * af);
            E = eta;
            F = bf / af * (eta - 1.0f);
        } else {
            E = 1.0f;
            F = bf * dt;
        }
        g_psi[m * CH + c] = make_float2(E, F * 16.0f);
        g_eul[m * CH + c] = make_float2(fmaf(ddt, af, 1.0f), (ddt * bf) * 16.0f);
    }

    for (int j = c; j < tail_n; j += 256) out_tail[j] = theta[j];
}

// ---------------------------------------------------------------------------
// Main transform in t-coordinates (t = p*16, t in [0,16)).
// Cell bits via the fp bias trick: bits = float_as_int(fadd_rd(t, 1.5*2^23)),
// low bits == floor(t) for t in [0, 2^22). Address index:
//     off = bits - 0x4B400000;  idx = umin(off, 15)
// Any t < 0 (out-of-domain lanes, discarded at the end) underflows off to a
// huge unsigned -> clamps to 15: memory-safe for every representable input,
// including NaN (bits large -> clamp). Cell stride = 256 ch * 8 B = 1<<11.
// ---------------------------------------------------------------------------
#define FBIAS 12582912.0f    // 1.5 * 2^23
#define BITS0 0x4B400000u

__device__ __forceinline__ unsigned tbits(float t)
{
    return (unsigned)__float_as_int(__fadd_rd(t, FBIAS));
}

__device__ __forceinline__ unsigned tidx(float t)
{
    return umin(tbits(t) - BITS0, 15u);
}

__global__ __launch_bounds__(1024, 2)
void cpab_main(const float* __restrict__ x, float* __restrict__ out, int Nrows)
{
    extern __shared__ float2 smem[];   // [0,4096): psi   [4096,8192): eul

    const int tid = threadIdx.x;
    for (int i = tid; i < NCELL * CH; i += 1024) {
        smem[i]              = g_psi[i];
        smem[NCELL * CH + i] = g_eul[i];
    }
    __syncthreads();

    const int ch = tid & 255;          // channel
    const int g  = tid >> 8;           // row group 0..3

    const char* psi_b = (const char*)smem + ch * 8;
    const char* eul_b = (const char*)smem + NCELL * CH * 8 + ch * 8;

    const int stride = gridDim.x * 8;
    int r0 = blockIdx.x * 8 + g * 2;
    if (r0 >= Nrows) return;

    float xv0 = x[(size_t)r0 * CH + ch];
    float xv1 = x[(size_t)(r0 + 1) * CH + ch];

    for (; r0 < Nrows; r0 += stride) {
        // prefetch next pair
        int rn = r0 + stride;
        float nx0 = 0.0f, nx1 = 0.0f;
        if (rn < Nrows) {
            nx0 = x[(size_t)rn * CH + ch];
            nx1 = x[(size_t)(rn + 1) * CH + ch];
        }

        float p0 = (xv0 + 3.0f) / 6.0f;
        float p1 = (xv1 + 3.0f) / 6.0f;
        bool ood0 = (p0 >= 1.0f) || (p0 <= 0.0f);
        bool ood1 = (p1 >= 1.0f) || (p1 <= 0.0f);

        // ood lanes: result discarded -> park at a mid-cell fixed start so
        // they ride the fast path (no divergence drag) and stay in-range.
        float q0 = ood0 ? 8.0f : p0 * 16.0f;
        float q1 = ood1 ? 8.0f : p1 * 16.0f;

        #pragma unroll 1
        for (int s = 0; s < 10; s++) {
            unsigned b0 = tbits(q0);
            unsigned b1 = tbits(q1);
            float2 ef0 = *(const float2*)(psi_b + ((size_t)umin(b0 - BITS0, 15u) << 11));
            float2 ef1 = *(const float2*)(psi_b + ((size_t)umin(b1 - BITS0, 15u) << 11));
            float pc0 = fmaf(ef0.x, q0, ef0.y);
            float pc1 = fmaf(ef1.x, q1, ef1.y);

            if (tbits(pc0) == b0) {
                q0 = pc0;
            } else {
                #pragma unroll
                for (int u = 0; u < 5; u++) {
                    float2 ab = *(const float2*)(eul_b + ((size_t)tidx(q0) << 11));
                    q0 = fmaf(ab.x, q0, ab.y);
                }
            }
            if (tbits(pc1) == b1) {
                q1 = pc1;
            } else {
                #pragma unroll
                for (int u = 0; u < 5; u++) {
                    float2 ab = *(const float2*)(eul_b + ((size_t)tidx(q1) << 11));
                    q1 = fmaf(ab.x, q1, ab.y);
                }
            }
        }

        out[(size_t)r0 * CH + ch]       = ood0 ? xv0 : fmaf(q0, 0.375f, -3.0f);
        out[(size_t)(r0 + 1) * CH + ch] = ood1 ? xv1 : fmaf(q1, 0.375f, -3.0f);

        xv0 = nx0;
        xv1 = nx1;
    }
}

// ---------------------------------------------------------------------------
extern "C" void kernel_launch(void* const* d_in, const int* in_sizes, int n_in,
                              void* d_out, int out_size)
{
    const float* x     = (const float*)d_in[0];
    const void*  timep = d_in[4];
    const float* theta = (const float*)d_in[5];
    const int xsz  = in_sizes[0];                 // N * 256
    const int thsz = in_sizes[5];                 // 256 * 15
    const int Nrows = xsz / CH;                   // even (131072)
    float* out = (float*)d_out;

    Basis bb;
    compute_basis_host(&bb);                      // pure host arithmetic

    cpab_setup<<<1, 256>>>(theta, timep, out + xsz, thsz, bb);

    const int smem_bytes = 2 * NCELL * CH * (int)sizeof(float2);   // 64 KB
    cudaFuncSetAttribute(cpab_main, cudaFuncAttributeMaxDynamicSharedMemorySize,
                         smem_bytes);

    int maxblocks = (Nrows + 7) / 8;
    int grid = 296 < maxblocks ? 296 : maxblocks;  // 148 SMs * 2 blocks
    cpab_main<<<grid, 1024, smem_bytes>>>(x, out, Nrows);
}

// round 14
// speedup vs baseline: 1.6327x; 1.6327x over previous
#include <cuda_runtime.h>
#include <math.h>

#define NCELL 16
#define CH    256

struct Basis { float B[32 * 15]; };   // B[k*15+j] = B_BASIS[k][j] (fp32)

// Tables in t-coordinates (t = p*16), per (cell m, channel c):
//  g_psi[m*CH+c] = (E, F16)   closed-form step  t' = E*t + F16   (F16 = 16*F)
//  g_eul[m*CH+c] = (EA,EB16)  Euler substep     t' = EA*t + EB16 (EB16 = 16*EB)
__device__ float2 g_psi[NCELL * CH];
__device__ float2 g_eul[NCELL * CH];

// ---------------------------------------------------------------------------
// Host: reproduce np.linalg.svd(L) null-space rows. LAPACK dgesdd Path 4t
// (M=17 < N=32, N >= MNTHR): rows 17..31 of VT are rows 17..31 of
// Q = H(17)...H(1) from the LQ factorization of L. Pure fp64 arithmetic,
// deterministic, depends only on compile-time constants -> host-side OK.
// ---------------------------------------------------------------------------
static void compute_basis_host(Basis* out)
{
    double Ad[17][32];
    double Qd[32][32];
    double tau[17];

    for (int i = 0; i < 17; i++)
        for (int j = 0; j < 32; j++) Ad[i][j] = 0.0;

    for (int k = 1; k < NCELL; k++) {
        double xk = (double)k / (double)NCELL;
        Ad[k - 1][2 * (k - 1)]     =  xk;
        Ad[k - 1][2 * (k - 1) + 1] =  1.0;
        Ad[k - 1][2 * k]           = -xk;
        Ad[k - 1][2 * k + 1]       = -1.0;
    }
    Ad[NCELL - 1][1]         = 1.0;
    Ad[NCELL][2 * NCELL - 2] = 1.0;
    Ad[NCELL][2 * NCELL - 1] = 1.0;

    // LQ with LAPACK dlarfg sign convention
    for (int i = 0; i < 17; i++) {
        double xn2 = 0.0;
        for (int j = i + 1; j < 32; j++) xn2 += Ad[i][j] * Ad[i][j];
        double alpha = Ad[i][i];
        if (xn2 == 0.0) {
            tau[i] = 0.0;
        } else {
            double r    = sqrt(alpha * alpha + xn2);
            double beta = (alpha >= 0.0) ? -r : r;
            tau[i] = (beta - alpha) / beta;
            double sc = 1.0 / (alpha - beta);
            for (int j = i + 1; j < 32; j++) Ad[i][j] *= sc;
            Ad[i][i] = beta;
        }
        double ti = tau[i];
        if (ti != 0.0) {
            for (int rr = i + 1; rr < 17; rr++) {
                double w = Ad[rr][i];
                for (int j = i + 1; j < 32; j++) w += Ad[rr][j] * Ad[i][j];
                w *= ti;
                Ad[rr][i] -= w;
                for (int j = i + 1; j < 32; j++) Ad[rr][j] -= w * Ad[i][j];
            }
        }
    }

    // Q = H(17)...H(1), applied to I (M := H(i)*M, i ascending)
    for (int i = 0; i < 32; i++)
        for (int j = 0; j < 32; j++) Qd[i][j] = (i == j) ? 1.0 : 0.0;

    for (int i = 0; i < 17; i++) {
        double ti = tau[i];
        if (ti == 0.0) continue;
        for (int jc = 0; jc < 32; jc++) {
            double s = Qd[i][jc];
            for (int j = i + 1; j < 32; j++) s += Ad[i][j] * Qd[j][jc];
            s *= ti;
            Qd[i][jc] -= s;
            for (int j = i + 1; j < 32; j++) Qd[j][jc] -= Ad[i][j] * s;
        }
    }

    // B_BASIS[k][j] = VT[17+j][k] = Qd[17+j][k], cast to fp32
    for (int k = 0; k < 32; k++)
        for (int j = 0; j < 15; j++)
            out->B[k * 15 + j] = (float)Qd[17 + j][k];
}

// ---------------------------------------------------------------------------
// Tiny setup kernel: per-(cell,channel) affine tables (t-coords) + theta copy.
// ---------------------------------------------------------------------------
__global__ void cpab_setup(const float* __restrict__ theta,
                           const void*  __restrict__ timep,
                           float* __restrict__ out_tail, int tail_n,
                           Basis bb)
{
    const int c = threadIdx.x;     // channel

    // time scalar: robust to int32/int64/float32 storage (value is 1)
    int   iv = *(const int*)timep;
    float fv = *(const float*)timep;
    float t;
    if (iv > 0 && iv < 1000000)        t = (float)iv;
    else if (fv > 0.0f && fv < 1.0e6f) t = fv;
    else                               t = 1.0f;
    float dt  = t / 10.0f;     // NSTEPS1 = 10
    float ddt = dt / 5.0f;     // NSTEPS2 = 5

    float th[15];
    #pragma unroll
    for (int j = 0; j < 15; j++) th[j] = theta[c * 15 + j];

    #pragma unroll
    for (int m = 0; m < NCELL; m++) {
        float af = 0.0f, bf = 0.0f;
        #pragma unroll
        for (int j = 0; j < 15; j++) {
            af = fmaf(th[j], bb.B[(2 * m) * 15 + j],     af);
            bf = fmaf(th[j], bb.B[(2 * m + 1) * 15 + j], bf);
        }
        float E, F;
        if (fabsf(af) > 1e-7f) {
            float eta = expf(dt * af);
            E = eta;
            F = bf / af * (eta - 1.0f);
        } else {
            E = 1.0f;
            F = bf * dt;
        }
        g_psi[m * CH + c] = make_float2(E, F * 16.0f);
        g_eul[m * CH + c] = make_float2(fmaf(ddt, af, 1.0f), (ddt * bf) * 16.0f);
    }

    for (int j = c; j < tail_n; j += 256) out_tail[j] = theta[j];
}

// ---------------------------------------------------------------------------
// Main transform in t-coordinates (t = p*16, t in [0,16)).
// Cell bits via the fp bias trick: bits = float_as_int(fadd_rd(t, 1.5*2^23)),
// low bits == floor(t) for t in [0, 2^22). Table index:
//     idx = umin(bits - 0x4B400000, 15)
// Negative t underflows to huge unsigned -> clamps to 15: memory-safe for
// every representable input. Cell stride = 256 ch * 8 B = 2048 bytes.
// R8's single paired Euler branch retained (per-point branches doubled the
// BSSY/BSYNC cost and regressed — R11 post-mortem).
// ---------------------------------------------------------------------------
#define FBIAS 12582912.0f    // 1.5 * 2^23
#define BITS0 0x4B400000u

__device__ __forceinline__ unsigned tbits(float t)
{
    return (unsigned)__float_as_int(__fadd_rd(t, FBIAS));
}

__device__ __forceinline__ unsigned tidx(float t)
{
    return umin(tbits(t) - BITS0, 15u);
}

__global__ __launch_bounds__(1024, 2)
void cpab_main(const float* __restrict__ x, float* __restrict__ out, int Nrows)
{
    extern __shared__ float2 smem[];   // [0,4096): psi   [4096,8192): eul

    const int tid = threadIdx.x;
    for (int i = tid; i < NCELL * CH; i += 1024) {
        smem[i]              = g_psi[i];
        smem[NCELL * CH + i] = g_eul[i];
    }
    __syncthreads();

    const int ch = tid & 255;          // channel
    const int g  = tid >> 8;           // row group 0..3

    const char* psi_b = (const char*)smem + ch * 8;
    const char* eul_b = (const char*)smem + NCELL * CH * 8 + ch * 8;

    for (int r0 = blockIdx.x * 8 + g * 2; r0 < Nrows; r0 += gridDim.x * 8) {
        const int r1 = r0 + 1;   // Nrows is even (131072)

        float xv0 = x[(size_t)r0 * CH + ch];
        float xv1 = x[(size_t)r1 * CH + ch];

        float p0 = (xv0 + 3.0f) / 6.0f;
        float p1 = (xv1 + 3.0f) / 6.0f;
        bool ood0 = (p0 >= 1.0f) || (p0 <= 0.0f);
        bool ood1 = (p1 >= 1.0f) || (p1 <= 0.0f);

        // ood lanes: result discarded -> park mid-cell so they ride the fast
        // path instead of dragging their warp into Euler every step.
        float q0 = ood0 ? 8.0f : p0 * 16.0f;
        float q1 = ood1 ? 8.0f : p1 * 16.0f;

        #pragma unroll 1
        for (int s = 0; s < 10; s++) {
            unsigned b0 = tbits(q0);
            unsigned b1 = tbits(q1);
            float2 ef0 = *(const float2*)(psi_b + (umin(b0 - BITS0, 15u) << 11));
            float2 ef1 = *(const float2*)(psi_b + (umin(b1 - BITS0, 15u) << 11));
            float pc0 = fmaf(ef0.x, q0, ef0.y);
            float pc1 = fmaf(ef1.x, q1, ef1.y);
            bool st0 = (tbits(pc0) == b0);
            bool st1 = (tbits(pc1) == b1);
            if (st0 & st1) {
                q0 = pc0;
                q1 = pc1;
            } else {
                float e0 = q0, e1 = q1;
                #pragma unroll
                for (int u = 0; u < 5; u++) {
                    float2 a0 = *(const float2*)(eul_b + (tidx(e0) << 11));
                    float2 a1 = *(const float2*)(eul_b + (tidx(e1) << 11));
                    e0 = fmaf(a0.x, e0, a0.y);
                    e1 = fmaf(a1.x, e1, a1.y);
                }
                q0 = st0 ? pc0 : e0;
                q1 = st1 ? pc1 : e1;
            }
        }

        out[(size_t)r0 * CH + ch] = ood0 ? xv0 : fmaf(q0, 0.375f, -3.0f);
        out[(size_t)r1 * CH + ch] = ood1 ? xv1 : fmaf(q1, 0.375f, -3.0f);
    }
}

// ---------------------------------------------------------------------------
extern "C" void kernel_launch(void* const* d_in, const int* in_sizes, int n_in,
                              void* d_out, int out_size)
{
    const float* x     = (const float*)d_in[0];
    const void*  timep = d_in[4];
    const float* theta = (const float*)d_in[5];
    const int xsz  = in_sizes[0];                 // N * 256
    const int thsz = in_sizes[5];                 // 256 * 15
    const int Nrows = xsz / CH;                   // even (131072)
    float* out = (float*)d_out;

    Basis bb;
    compute_basis_host(&bb);                      // pure host arithmetic

    cpab_setup<<<1, 256>>>(theta, timep, out + xsz, thsz, bb);

    const int smem_bytes = 2 * NCELL * CH * (int)sizeof(float2);   // 64 KB
    cudaFuncSetAttribute(cpab_main, cudaFuncAttributeMaxDynamicSharedMemorySize,
                         smem_bytes);

    int maxblocks = (Nrows + 7) / 8;
    int grid = 296 < maxblocks ? 296 : maxblocks;  // 148 SMs * 2 blocks
    cpab_main<<<grid, 1024, smem_bytes>>>(x, out, Nrows);
}